// round 13
// baseline (speedup 1.0000x reference)
#include <cuda_runtime.h>
#include <cuda_fp16.h>
#include <cstdint>

// x: [4, 2048, 512] fp32; W*: [512,512]; b*: [512]; out fp32.

// fp16 scratch (static device globals — allocation-free)
__device__ __half g_xh[8192 * 512];
__device__ __half g_Wh[4 * 512 * 512];     // q,k,v,o
__device__ __half g_Qh[4 * 8 * 2048 * 64]; // [b][h][n][d], pre-scaled by EXPSCALE
__device__ __half g_Kh[4 * 8 * 2048 * 64];
__device__ __half g_Vh[4 * 8 * 2048 * 64];
__device__ __half g_atth[8192 * 512];

// log2(e)/sqrt(512): folded into Q so softmax is a bare ex2.approx
#define EXPSCALE 0.06375872f

// h2(1.0, 1.0) — B-fragment constant for row-sum-via-MMA
#define ONES_H2 0x3C003C00u

// ---------------------------------------------------------------------------
// PTX wrappers
// ---------------------------------------------------------------------------
__device__ __forceinline__ void mma_f16(
    float& d0, float& d1, float& d2, float& d3,
    uint32_t a0, uint32_t a1, uint32_t a2, uint32_t a3,
    uint32_t b0, uint32_t b1)
{
    asm volatile(
        "mma.sync.aligned.m16n8k16.row.col.f32.f16.f16.f32 "
        "{%0,%1,%2,%3}, {%4,%5,%6,%7}, {%8,%9}, {%0,%1,%2,%3};\n"
        : "+f"(d0), "+f"(d1), "+f"(d2), "+f"(d3)
        : "r"(a0), "r"(a1), "r"(a2), "r"(a3), "r"(b0), "r"(b1));
}

__device__ __forceinline__ void ldm_x4(
    uint32_t& r0, uint32_t& r1, uint32_t& r2, uint32_t& r3, uint32_t addr)
{
    asm volatile("ldmatrix.sync.aligned.m8n8.x4.shared.b16 {%0,%1,%2,%3}, [%4];"
                 : "=r"(r0), "=r"(r1), "=r"(r2), "=r"(r3) : "r"(addr));
}

__device__ __forceinline__ void ldm_x4_t(
    uint32_t& r0, uint32_t& r1, uint32_t& r2, uint32_t& r3, uint32_t addr)
{
    asm volatile("ldmatrix.sync.aligned.m8n8.x4.trans.shared.b16 {%0,%1,%2,%3}, [%4];"
                 : "=r"(r0), "=r"(r1), "=r"(r2), "=r"(r3) : "r"(addr));
}

// pack two f32 into f16x2: lo = a, hi = b (first PTX source is the UPPER half)
__device__ __forceinline__ uint32_t cvt_h2(float lo, float hi) {
    uint32_t r;
    asm("cvt.rn.f16x2.f32 %0, %1, %2;" : "=r"(r) : "f"(hi), "f"(lo));
    return r;
}

// 2^x on both fp16 lanes (MUFU, one op per pair)
__device__ __forceinline__ uint32_t ex2_h2(uint32_t x) {
    uint32_t r;
    asm("ex2.approx.f16x2 %0, %1;" : "=r"(r) : "r"(x));
    return r;
}

#define CP16(dst, src) \
    asm volatile("cp.async.cg.shared.global [%0], [%1], 16;" :: "r"(dst), "l"(src))
#define CPCOMMIT() asm volatile("cp.async.commit_group;")
#define CPWAIT1()  asm volatile("cp.async.wait_group 1;")
#define CPWAIT0()  asm volatile("cp.async.wait_group 0;")

__device__ __forceinline__ uint32_t smem_u32(const void* p) {
    return (uint32_t)__cvta_generic_to_shared(p);
}

// ---------------------------------------------------------------------------
// Prep: fp32 -> fp16 for x and the four weight matrices.
// ---------------------------------------------------------------------------
__global__ void prep_kernel(const float* __restrict__ x,
                            const float* __restrict__ Wq,
                            const float* __restrict__ Wk,
                            const float* __restrict__ Wv,
                            const float* __restrict__ Wo)
{
    const int NX = 8192 * 512 / 4;
    const int NW = 512 * 512 / 4;
    const int total = NX + 4 * NW;
    for (int i = blockIdx.x * blockDim.x + threadIdx.x; i < total;
         i += gridDim.x * blockDim.x) {
        const float4* src;
        __half* dst;
        int off;
        if (i < NX) { src = (const float4*)x; dst = g_xh; off = i; }
        else {
            int j = i - NX, w = j / NW; off = j - w * NW;
            src = (const float4*)((w == 0) ? Wq : (w == 1) ? Wk : (w == 2) ? Wv : Wo);
            dst = g_Wh + w * 512 * 512;
        }
        const float4 v = src[off];
        __half2* d2 = (__half2*)(dst + off * 4);
        d2[0] = __floats2half2_rn(v.x, v.y);
        d2[1] = __floats2half2_rn(v.z, v.w);
    }
}

// ---------------------------------------------------------------------------
// fp16 tensor-core GEMM: C[M,512] = X @ W^T + bias
// THIS ROUND: BK 32 -> 64. Halves the barrier count (8 k-iterations),
// doubles the MMA work per barrier (4 k-chunks, 64 HMMA). Pitch 144 B is
// conflict-free for ldmatrix (rows stride 4 banks; 8 rows tile 32 banks).
// 256 threads = 8 warps (2m x 4n), warp tile 64x32, 3-stage cp.async.
// ---------------------------------------------------------------------------
#define GPIT 144                      // bytes/row: 64 fp16 + 8 pad
#define GBUFB (128 * GPIT)            // 18432 B per operand per stage
#define GEMM_SMEM (6 * GBUFB)         // 110592 B (x2 CTAs fits 228KB)

__global__ __launch_bounds__(256, 2) void gemm_f16(
    const float* __restrict__ bq, const float* __restrict__ bk,
    const float* __restrict__ bv, float* __restrict__ Oout, int mode)
{
    extern __shared__ char smg[];
    const uint32_t xs0 = smem_u32(smg);
    const uint32_t ws0 = xs0 + 3 * GBUFB;

    const int tid  = threadIdx.x;
    const int lane = tid & 31;
    const int warp = tid >> 5;
    const int g    = lane >> 2;
    const int t4   = lane & 3;
    const int lj   = lane >> 3;
    const int lr   = lane & 7;
    const int wm   = warp >> 2;
    const int wn   = warp & 3;
    const int m0   = blockIdx.y * 128;
    const int n0   = blockIdx.x * 128;
    const int z    = blockIdx.z;

    const __half* Xh = (mode == 0) ? g_xh : g_atth;
    const __half* Wh = g_Wh + (size_t)((mode == 0) ? z : 3) * 512 * 512;

    // staging: 128 rows x 128 B per operand per stage; thread does a 64 B run
    const int srow = tid >> 1;           // 0..127
    const int shalf = (tid & 1) * 4;     // 16B-seg base: 0 or 4

    auto stage = [&](int kt, int buf) {
#pragma unroll
        for (int i = 0; i < 4; ++i) {
            const int seg = shalf + i;
            const int kk = kt * 64 + seg * 8;
            CP16(xs0 + buf * GBUFB + srow * GPIT + seg * 16,
                 Xh + (size_t)(m0 + srow) * 512 + kk);
            CP16(ws0 + buf * GBUFB + srow * GPIT + seg * 16,
                 Wh + (size_t)(n0 + srow) * 512 + kk);
        }
    };

    float d[4][4][4];
#pragma unroll
    for (int mi = 0; mi < 4; ++mi)
#pragma unroll
        for (int ni = 0; ni < 4; ++ni)
#pragma unroll
            for (int c = 0; c < 4; ++c) d[mi][ni][c] = 0.0f;

    stage(0, 0); CPCOMMIT();
    stage(1, 1); CPCOMMIT();

    for (int kt = 0; kt < 8; ++kt) {
        if (kt < 7) CPWAIT1(); else CPWAIT0();
        __syncthreads();
        if (kt < 6) { stage(kt + 2, (kt + 2) % 3); CPCOMMIT(); }

        const int cur = kt % 3;
        const uint32_t xb = xs0 + cur * GBUFB;
        const uint32_t wb = ws0 + cur * GBUFB;
#pragma unroll
        for (int kc = 0; kc < 4; ++kc) {
            uint32_t a[4][4];
#pragma unroll
            for (int mi = 0; mi < 4; ++mi)
                ldm_x4(a[mi][0], a[mi][1], a[mi][2], a[mi][3],
                       xb + (wm * 64 + mi * 16 + (lj & 1) * 8 + lr) * GPIT
                          + (kc * 16 + (lj >> 1) * 8) * 2);
            uint32_t bf[4][2];
#pragma unroll
            for (int nb = 0; nb < 2; ++nb) {
                uint32_t r0, r1, r2, r3;
                ldm_x4(r0, r1, r2, r3,
                       wb + (wn * 32 + nb * 16 + (lj >> 1) * 8 + lr) * GPIT
                          + (kc * 16 + (lj & 1) * 8) * 2);
                bf[2 * nb][0] = r0; bf[2 * nb][1] = r1;
                bf[2 * nb + 1][0] = r2; bf[2 * nb + 1][1] = r3;
            }
#pragma unroll
            for (int mi = 0; mi < 4; ++mi)
#pragma unroll
                for (int ni = 0; ni < 4; ++ni)
                    mma_f16(d[mi][ni][0], d[mi][ni][1], d[mi][ni][2], d[mi][ni][3],
                            a[mi][0], a[mi][1], a[mi][2], a[mi][3],
                            bf[ni][0], bf[ni][1]);
        }
    }

    if (mode == 0) {
        const float* bias = (z == 0) ? bq : (z == 1) ? bk : bv;
        const float qsc = (z == 0) ? EXPSCALE : 1.0f;
        __half* O = (z == 0) ? g_Qh : (z == 1) ? g_Kh : g_Vh;
#pragma unroll
        for (int ni = 0; ni < 4; ++ni) {
            const int col = n0 + wn * 32 + ni * 8 + 2 * t4;
            const float bb0 = bias[col], bb1 = bias[col + 1];
            const int h_ = col >> 6, dd = col & 63;
#pragma unroll
            for (int mi = 0; mi < 4; ++mi) {
                const int row = m0 + wm * 64 + mi * 16 + g;
                const int b0_ = row >> 11, n0_ = row & 2047;
                const int b1_ = (row + 8) >> 11, n1_ = (row + 8) & 2047;
                *(__half2*)&O[(((size_t)(b0_ * 8 + h_) * 2048) + n0_) * 64 + dd] =
                    __floats2half2_rn((d[mi][ni][0] + bb0) * qsc,
                                      (d[mi][ni][1] + bb1) * qsc);
                *(__half2*)&O[(((size_t)(b1_ * 8 + h_) * 2048) + n1_) * 64 + dd] =
                    __floats2half2_rn((d[mi][ni][2] + bb0) * qsc,
                                      (d[mi][ni][3] + bb1) * qsc);
            }
        }
    } else {
        const float* bo = bq;
        float* O = Oout;
#pragma unroll
        for (int ni = 0; ni < 4; ++ni) {
            const int col = n0 + wn * 32 + ni * 8 + 2 * t4;
            const float bb0 = bo[col], bb1 = bo[col + 1];
#pragma unroll
            for (int mi = 0; mi < 4; ++mi) {
                const int row = m0 + wm * 64 + mi * 16 + g;
                *(float2*)&O[(size_t)row * 512 + col] =
                    make_float2(d[mi][ni][0] + bb0, d[mi][ni][1] + bb1);
                *(float2*)&O[(size_t)(row + 8) * 512 + col] =
                    make_float2(d[mi][ni][2] + bb0, d[mi][ni][3] + bb1);
            }
        }
    }
}

// ---------------------------------------------------------------------------
// fp16 flash attention, FA2-style, register-lean (2 CTAs/SM). Unchanged.
// exp via ex2.approx.f16x2; row sums via ones-MMA on the tensor pipe.
// ---------------------------------------------------------------------------
#define KVPIT 144                       // 64 fp16 + 8 pad
#define KVBUF (128 * KVPIT)             // 18432 B per operand per stage
#define ATT_SMEM (6 * KVBUF)            // 110592 B (x2 CTAs fits 228KB)

__global__ __launch_bounds__(256, 2) void attn_f16()
{
    extern __shared__ char sma[];
    const uint32_t ks0 = smem_u32(sma);
    const uint32_t vs0 = ks0 + 3 * KVBUF;

    const int tid  = threadIdx.x;
    const int lane = tid & 31;
    const int warp = tid >> 5;
    const int g    = lane >> 2;
    const int t4   = lane & 3;
    const int lj   = lane >> 3;
    const int lr   = lane & 7;
    const int qt   = blockIdx.x;
    const int bh   = blockIdx.y;

    const __half* Qg = g_Qh + (size_t)bh * (2048 * 64) + (size_t)qt * 128 * 64;
    const __half* Kg = g_Kh + (size_t)bh * (2048 * 64);
    const __half* Vg = g_Vh + (size_t)bh * (2048 * 64);

    const int row_s = warp * 16 + g;

    uint32_t qf[4][4];
#pragma unroll
    for (int kc = 0; kc < 4; ++kc) {
        qf[kc][0] = *(const uint32_t*)(Qg + row_s * 64 + kc * 16 + 2 * t4);
        qf[kc][1] = *(const uint32_t*)(Qg + (row_s + 8) * 64 + kc * 16 + 2 * t4);
        qf[kc][2] = *(const uint32_t*)(Qg + row_s * 64 + kc * 16 + 8 + 2 * t4);
        qf[kc][3] = *(const uint32_t*)(Qg + (row_s + 8) * 64 + kc * 16 + 8 + 2 * t4);
    }

    const int srow = tid >> 3;
    const int sseg = tid & 7;
    auto stage = [&](int kt, int buf) {
        const __half* Ksrc = Kg + (size_t)kt * 128 * 64;
        const __half* Vsrc = Vg + (size_t)kt * 128 * 64;
#pragma unroll
        for (int i = 0; i < 4; ++i) {
            const int r = srow + 32 * i;
            CP16(ks0 + buf * KVBUF + r * KVPIT + sseg * 16, Ksrc + r * 64 + sseg * 8);
            CP16(vs0 + buf * KVBUF + r * KVPIT + sseg * 16, Vsrc + r * 64 + sseg * 8);
        }
    };

    float o[8][4];
#pragma unroll
    for (int ni = 0; ni < 8; ++ni)
#pragma unroll
        for (int c = 0; c < 4; ++c) o[ni][c] = 0.0f;
    float osum[4] = {0.0f, 0.0f, 0.0f, 0.0f};

    stage(0, 0); CPCOMMIT();
    stage(1, 1); CPCOMMIT();

    for (int kt = 0; kt < 16; ++kt) {
        if (kt < 15) CPWAIT1(); else CPWAIT0();
        __syncthreads();
        if (kt < 14) { stage(kt + 2, (kt + 2) % 3); CPCOMMIT(); }

        const int cur = kt % 3;
        const uint32_t ksb = ks0 + cur * KVBUF;
        const uint32_t vsb = vs0 + cur * KVBUF;

#pragma unroll
        for (int h = 0; h < 2; ++h) {
            float s[8][4];
#pragma unroll
            for (int ni = 0; ni < 8; ++ni)
#pragma unroll
                for (int c = 0; c < 4; ++c) s[ni][c] = 0.0f;

#pragma unroll
            for (int kc = 0; kc < 4; ++kc) {
#pragma unroll
                for (int nb = 0; nb < 4; ++nb) {
                    uint32_t r0, r1, r2, r3;
                    ldm_x4(r0, r1, r2, r3,
                           ksb + (h * 64 + nb * 16 + (lj >> 1) * 8 + lr) * KVPIT
                               + (kc * 16 + (lj & 1) * 8) * 2);
                    mma_f16(s[2 * nb][0], s[2 * nb][1], s[2 * nb][2], s[2 * nb][3],
                            qf[kc][0], qf[kc][1], qf[kc][2], qf[kc][3], r0, r1);
                    mma_f16(s[2 * nb + 1][0], s[2 * nb + 1][1],
                            s[2 * nb + 1][2], s[2 * nb + 1][3],
                            qf[kc][0], qf[kc][1], qf[kc][2], qf[kc][3], r2, r3);
                }
            }

            uint32_t pa[4][4];
#pragma unroll
            for (int kc = 0; kc < 4; ++kc) {
                pa[kc][0] = ex2_h2(cvt_h2(s[2 * kc][0],     s[2 * kc][1]));
                pa[kc][1] = ex2_h2(cvt_h2(s[2 * kc][2],     s[2 * kc][3]));
                pa[kc][2] = ex2_h2(cvt_h2(s[2 * kc + 1][0], s[2 * kc + 1][1]));
                pa[kc][3] = ex2_h2(cvt_h2(s[2 * kc + 1][2], s[2 * kc + 1][3]));
            }

#pragma unroll
            for (int kc = 0; kc < 4; ++kc)
                mma_f16(osum[0], osum[1], osum[2], osum[3],
                        pa[kc][0], pa[kc][1], pa[kc][2], pa[kc][3],
                        ONES_H2, ONES_H2);

#pragma unroll
            for (int kc = 0; kc < 4; ++kc) {
#pragma unroll
                for (int np = 0; np < 4; ++np) {
                    uint32_t v0, v1, v2, v3;
                    ldm_x4_t(v0, v1, v2, v3,
                             vsb + (h * 64 + kc * 16 + (lj & 1) * 8 + lr) * KVPIT
                                 + (np * 16 + (lj >> 1) * 8) * 2);
                    mma_f16(o[2 * np][0], o[2 * np][1], o[2 * np][2], o[2 * np][3],
                            pa[kc][0], pa[kc][1], pa[kc][2], pa[kc][3], v0, v1);
                    mma_f16(o[2 * np + 1][0], o[2 * np + 1][1],
                            o[2 * np + 1][2], o[2 * np + 1][3],
                            pa[kc][0], pa[kc][1], pa[kc][2], pa[kc][3], v2, v3);
                }
            }
        }
    }

    const float inv0 = 1.0f / osum[0];
    const float inv1 = 1.0f / osum[2];

    const int b_ = bh >> 3, h_ = bh & 7;
    const int row0 = b_ * 2048 + qt * 128 + row_s;
#pragma unroll
    for (int ni = 0; ni < 8; ++ni) {
        const int col = h_ * 64 + ni * 8 + 2 * t4;
        *(__half2*)&g_atth[(size_t)row0 * 512 + col] =
            __floats2half2_rn(o[ni][0] * inv0, o[ni][1] * inv0);
        *(__half2*)&g_atth[(size_t)(row0 + 8) * 512 + col] =
            __floats2half2_rn(o[ni][2] * inv1, o[ni][3] * inv1);
    }
}

// ---------------------------------------------------------------------------
// Launch
// ---------------------------------------------------------------------------
extern "C" void kernel_launch(void* const* d_in, const int* in_sizes, int n_in,
                              void* d_out, int out_size)
{
    const float* x  = (const float*)d_in[0];
    const float* Wq = (const float*)d_in[1];
    const float* bq = (const float*)d_in[2];
    const float* Wk = (const float*)d_in[3];
    const float* bk = (const float*)d_in[4];
    const float* Wv = (const float*)d_in[5];
    const float* bv = (const float*)d_in[6];
    const float* Wo = (const float*)d_in[7];
    const float* bo = (const float*)d_in[8];
    float* out = (float*)d_out;

    cudaFuncSetAttribute(gemm_f16,
                         cudaFuncAttributeMaxDynamicSharedMemorySize, GEMM_SMEM);
    cudaFuncSetAttribute(attn_f16,
                         cudaFuncAttributeMaxDynamicSharedMemorySize, ATT_SMEM);

    prep_kernel<<<1024, 256>>>(x, Wq, Wk, Wv, Wo);

    gemm_f16<<<dim3(4, 64, 3), 256, GEMM_SMEM>>>(bq, bk, bv, nullptr, 0);

    attn_f16<<<dim3(16, 32), 256, ATT_SMEM>>>();

    gemm_f16<<<dim3(4, 64, 1), 256, GEMM_SMEM>>>(bo, nullptr, nullptr, out, 1);
}

// round 14
// speedup vs baseline: 1.1872x; 1.1872x over previous
#include <cuda_runtime.h>
#include <cuda_fp16.h>
#include <cstdint>

// x: [4, 2048, 512] fp32; W*: [512,512]; b*: [512]; out fp32.

// fp16 scratch (static device globals — allocation-free)
__device__ __half g_xh[8192 * 512];
__device__ __half g_Wh[4 * 512 * 512];     // q,k,v,o
__device__ __half g_Qh[4 * 8 * 2048 * 64]; // [b][h][n][d], pre-scaled by EXPSCALE
__device__ __half g_Kh[4 * 8 * 2048 * 64];
__device__ __half g_Vh[4 * 8 * 2048 * 64];
__device__ __half g_atth[8192 * 512];

// log2(e)/sqrt(512): folded into Q so softmax is a bare ex2.approx
#define EXPSCALE 0.06375872f

// h2(1.0, 1.0) — B-fragment constant for row-sum-via-MMA
#define ONES_H2 0x3C003C00u

// ---------------------------------------------------------------------------
// PTX wrappers
// ---------------------------------------------------------------------------
__device__ __forceinline__ void mma_f16(
    float& d0, float& d1, float& d2, float& d3,
    uint32_t a0, uint32_t a1, uint32_t a2, uint32_t a3,
    uint32_t b0, uint32_t b1)
{
    asm volatile(
        "mma.sync.aligned.m16n8k16.row.col.f32.f16.f16.f32 "
        "{%0,%1,%2,%3}, {%4,%5,%6,%7}, {%8,%9}, {%0,%1,%2,%3};\n"
        : "+f"(d0), "+f"(d1), "+f"(d2), "+f"(d3)
        : "r"(a0), "r"(a1), "r"(a2), "r"(a3), "r"(b0), "r"(b1));
}

__device__ __forceinline__ void ldm_x4(
    uint32_t& r0, uint32_t& r1, uint32_t& r2, uint32_t& r3, uint32_t addr)
{
    asm volatile("ldmatrix.sync.aligned.m8n8.x4.shared.b16 {%0,%1,%2,%3}, [%4];"
                 : "=r"(r0), "=r"(r1), "=r"(r2), "=r"(r3) : "r"(addr));
}

__device__ __forceinline__ void ldm_x4_t(
    uint32_t& r0, uint32_t& r1, uint32_t& r2, uint32_t& r3, uint32_t addr)
{
    asm volatile("ldmatrix.sync.aligned.m8n8.x4.trans.shared.b16 {%0,%1,%2,%3}, [%4];"
                 : "=r"(r0), "=r"(r1), "=r"(r2), "=r"(r3) : "r"(addr));
}

// pack two f32 into f16x2: lo, hi (first PTX source is the UPPER half)
__device__ __forceinline__ uint32_t cvt_h2(float lo, float hi) {
    uint32_t r;
    asm("cvt.rn.f16x2.f32 %0, %1, %2;" : "=r"(r) : "f"(hi), "f"(lo));
    return r;
}

// 2^x on both fp16 lanes (MUFU, one op per pair)
__device__ __forceinline__ uint32_t ex2_h2(uint32_t x) {
    uint32_t r;
    asm("ex2.approx.f16x2 %0, %1;" : "=r"(r) : "r"(x));
    return r;
}

#define CP16(dst, src) \
    asm volatile("cp.async.cg.shared.global [%0], [%1], 16;" :: "r"(dst), "l"(src))
#define CPCOMMIT() asm volatile("cp.async.commit_group;")
#define CPWAIT1()  asm volatile("cp.async.wait_group 1;")
#define CPWAIT0()  asm volatile("cp.async.wait_group 0;")

__device__ __forceinline__ uint32_t smem_u32(const void* p) {
    return (uint32_t)__cvta_generic_to_shared(p);
}

// ---------------------------------------------------------------------------
// Prep: fp32 -> fp16 for x and the four weight matrices.
// ---------------------------------------------------------------------------
__global__ void prep_kernel(const float* __restrict__ x,
                            const float* __restrict__ Wq,
                            const float* __restrict__ Wk,
                            const float* __restrict__ Wv,
                            const float* __restrict__ Wo)
{
    const int NX = 8192 * 512 / 4;
    const int NW = 512 * 512 / 4;
    const int total = NX + 4 * NW;
    for (int i = blockIdx.x * blockDim.x + threadIdx.x; i < total;
         i += gridDim.x * blockDim.x) {
        const float4* src;
        __half* dst;
        int off;
        if (i < NX) { src = (const float4*)x; dst = g_xh; off = i; }
        else {
            int j = i - NX, w = j / NW; off = j - w * NW;
            src = (const float4*)((w == 0) ? Wq : (w == 1) ? Wk : (w == 2) ? Wv : Wo);
            dst = g_Wh + w * 512 * 512;
        }
        const float4 v = src[off];
        __half2* d2 = (__half2*)(dst + off * 4);
        d2[0] = __floats2half2_rn(v.x, v.y);
        d2[1] = __floats2half2_rn(v.z, v.w);
    }
}

// ---------------------------------------------------------------------------
// fp16 tensor-core GEMM: C[M,512] = X @ W^T + bias  (REVERTED to R12: BK=32)
// 256 threads = 8 warps (2m x 4n), warp tile 64x32, 3-stage cp.async,
// ONE __syncthreads per k-iteration.
// ---------------------------------------------------------------------------
#define GPIT 80
#define GBUFB (128 * GPIT)            // 10240 B per operand per stage
#define GEMM_SMEM (6 * GBUFB)         // 61440 B

__global__ __launch_bounds__(256, 2) void gemm_f16(
    const float* __restrict__ bq, const float* __restrict__ bk,
    const float* __restrict__ bv, float* __restrict__ Oout, int mode)
{
    extern __shared__ char smg[];
    const uint32_t xs0 = smem_u32(smg);
    const uint32_t ws0 = xs0 + 3 * GBUFB;

    const int tid  = threadIdx.x;
    const int lane = tid & 31;
    const int warp = tid >> 5;
    const int g    = lane >> 2;
    const int t4   = lane & 3;
    const int lj   = lane >> 3;
    const int lr   = lane & 7;
    const int wm   = warp >> 2;
    const int wn   = warp & 3;
    const int m0   = blockIdx.y * 128;
    const int n0   = blockIdx.x * 128;
    const int z    = blockIdx.z;

    const __half* Xh = (mode == 0) ? g_xh : g_atth;
    const __half* Wh = g_Wh + (size_t)((mode == 0) ? z : 3) * 512 * 512;

    const int srow = tid >> 2;
    const int sseg = tid & 3;

    auto stage = [&](int kt, int buf) {
        const int kk = kt * 32 + sseg * 8;
#pragma unroll
        for (int i = 0; i < 2; ++i) {
            const int r = srow + 64 * i;
            CP16(xs0 + buf * GBUFB + r * GPIT + sseg * 16,
                 Xh + (size_t)(m0 + r) * 512 + kk);
            CP16(ws0 + buf * GBUFB + r * GPIT + sseg * 16,
                 Wh + (size_t)(n0 + r) * 512 + kk);
        }
    };

    float d[4][4][4];
#pragma unroll
    for (int mi = 0; mi < 4; ++mi)
#pragma unroll
        for (int ni = 0; ni < 4; ++ni)
#pragma unroll
            for (int c = 0; c < 4; ++c) d[mi][ni][c] = 0.0f;

    stage(0, 0); CPCOMMIT();
    stage(1, 1); CPCOMMIT();

    for (int kt = 0; kt < 16; ++kt) {
        if (kt < 15) CPWAIT1(); else CPWAIT0();
        __syncthreads();
        if (kt < 14) { stage(kt + 2, (kt + 2) % 3); CPCOMMIT(); }

        const int cur = kt % 3;
        const uint32_t xb = xs0 + cur * GBUFB;
        const uint32_t wb = ws0 + cur * GBUFB;
#pragma unroll
        for (int kc = 0; kc < 2; ++kc) {
            uint32_t a[4][4];
#pragma unroll
            for (int mi = 0; mi < 4; ++mi)
                ldm_x4(a[mi][0], a[mi][1], a[mi][2], a[mi][3],
                       xb + (wm * 64 + mi * 16 + (lj & 1) * 8 + lr) * GPIT
                          + (kc * 16 + (lj >> 1) * 8) * 2);
            uint32_t bf[4][2];
#pragma unroll
            for (int nb = 0; nb < 2; ++nb) {
                uint32_t r0, r1, r2, r3;
                ldm_x4(r0, r1, r2, r3,
                       wb + (wn * 32 + nb * 16 + (lj >> 1) * 8 + lr) * GPIT
                          + (kc * 16 + (lj & 1) * 8) * 2);
                bf[2 * nb][0] = r0; bf[2 * nb][1] = r1;
                bf[2 * nb + 1][0] = r2; bf[2 * nb + 1][1] = r3;
            }
#pragma unroll
            for (int mi = 0; mi < 4; ++mi)
#pragma unroll
                for (int ni = 0; ni < 4; ++ni)
                    mma_f16(d[mi][ni][0], d[mi][ni][1], d[mi][ni][2], d[mi][ni][3],
                            a[mi][0], a[mi][1], a[mi][2], a[mi][3],
                            bf[ni][0], bf[ni][1]);
        }
    }

    if (mode == 0) {
        const float* bias = (z == 0) ? bq : (z == 1) ? bk : bv;
        const float qsc = (z == 0) ? EXPSCALE : 1.0f;
        __half* O = (z == 0) ? g_Qh : (z == 1) ? g_Kh : g_Vh;
#pragma unroll
        for (int ni = 0; ni < 4; ++ni) {
            const int col = n0 + wn * 32 + ni * 8 + 2 * t4;
            const float bb0 = bias[col], bb1 = bias[col + 1];
            const int h_ = col >> 6, dd = col & 63;
#pragma unroll
            for (int mi = 0; mi < 4; ++mi) {
                const int row = m0 + wm * 64 + mi * 16 + g;
                const int b0_ = row >> 11, n0_ = row & 2047;
                const int b1_ = (row + 8) >> 11, n1_ = (row + 8) & 2047;
                *(__half2*)&O[(((size_t)(b0_ * 8 + h_) * 2048) + n0_) * 64 + dd] =
                    __floats2half2_rn((d[mi][ni][0] + bb0) * qsc,
                                      (d[mi][ni][1] + bb1) * qsc);
                *(__half2*)&O[(((size_t)(b1_ * 8 + h_) * 2048) + n1_) * 64 + dd] =
                    __floats2half2_rn((d[mi][ni][2] + bb0) * qsc,
                                      (d[mi][ni][3] + bb1) * qsc);
            }
        }
    } else {
        const float* bo = bq;
        float* O = Oout;
#pragma unroll
        for (int ni = 0; ni < 4; ++ni) {
            const int col = n0 + wn * 32 + ni * 8 + 2 * t4;
            const float bb0 = bo[col], bb1 = bo[col + 1];
#pragma unroll
            for (int mi = 0; mi < 4; ++mi) {
                const int row = m0 + wm * 64 + mi * 16 + g;
                *(float2*)&O[(size_t)row * 512 + col] =
                    make_float2(d[mi][ni][0] + bb0, d[mi][ni][1] + bb1);
                *(float2*)&O[(size_t)(row + 8) * 512 + col] =
                    make_float2(d[mi][ni][2] + bb0, d[mi][ni][3] + bb1);
            }
        }
    }
}

// ---------------------------------------------------------------------------
// fp16 flash attention, FA2-style.
// THIS ROUND: 128 threads = 4 warps; each warp owns 32 q-rows (2 m-tiles).
// Every K/V ldmatrix now feeds both m-tiles -> per-SM smem traffic halves
// (it was co-binding with the tensor pipe). kv tile processed in four
// 32-col quarters to keep the live register set ~170 (2 CTAs/SM).
// exp via ex2.approx.f16x2; row sums via ones-MMA on the tensor pipe.
// ---------------------------------------------------------------------------
#define KVPIT 144                       // 64 fp16 + 8 pad
#define KVBUF (128 * KVPIT)             // 18432 B per operand per stage
#define ATT_SMEM (6 * KVBUF)            // 110592 B (x2 CTAs fits 228KB)

__global__ __launch_bounds__(128, 2) void attn_f16()
{
    extern __shared__ char sma[];
    const uint32_t ks0 = smem_u32(sma);
    const uint32_t vs0 = ks0 + 3 * KVBUF;

    const int tid  = threadIdx.x;
    const int lane = tid & 31;
    const int warp = tid >> 5;          // 0..3
    const int g    = lane >> 2;
    const int t4   = lane & 3;
    const int lj   = lane >> 3;
    const int lr   = lane & 7;
    const int qt   = blockIdx.x;
    const int bh   = blockIdx.y;

    const __half* Qg = g_Qh + (size_t)bh * (2048 * 64) + (size_t)qt * 128 * 64;
    const __half* Kg = g_Kh + (size_t)bh * (2048 * 64);
    const __half* Vg = g_Vh + (size_t)bh * (2048 * 64);

    // Two m-tiles per warp: rows warp*32 + mi*16 + {g, g+8}
    uint32_t qf[2][4][4];
#pragma unroll
    for (int mi = 0; mi < 2; ++mi) {
        const int rs = warp * 32 + mi * 16 + g;
#pragma unroll
        for (int kc = 0; kc < 4; ++kc) {
            qf[mi][kc][0] = *(const uint32_t*)(Qg + rs * 64 + kc * 16 + 2 * t4);
            qf[mi][kc][1] = *(const uint32_t*)(Qg + (rs + 8) * 64 + kc * 16 + 2 * t4);
            qf[mi][kc][2] = *(const uint32_t*)(Qg + rs * 64 + kc * 16 + 8 + 2 * t4);
            qf[mi][kc][3] = *(const uint32_t*)(Qg + (rs + 8) * 64 + kc * 16 + 8 + 2 * t4);
        }
    }

    // staging with 128 threads: 8 segs/thread/operand
    const int srow = tid >> 3;          // 0..15 (+16*i)
    const int sseg = tid & 7;
    auto stage = [&](int kt, int buf) {
        const __half* Ksrc = Kg + (size_t)kt * 128 * 64;
        const __half* Vsrc = Vg + (size_t)kt * 128 * 64;
#pragma unroll
        for (int i = 0; i < 8; ++i) {
            const int r = srow + 16 * i;
            CP16(ks0 + buf * KVBUF + r * KVPIT + sseg * 16, Ksrc + r * 64 + sseg * 8);
            CP16(vs0 + buf * KVBUF + r * KVPIT + sseg * 16, Vsrc + r * 64 + sseg * 8);
        }
    };

    float o[2][8][4];
#pragma unroll
    for (int mi = 0; mi < 2; ++mi)
#pragma unroll
        for (int ni = 0; ni < 8; ++ni)
#pragma unroll
            for (int c = 0; c < 4; ++c) o[mi][ni][c] = 0.0f;
    float osum[2][4] = {{0.0f, 0.0f, 0.0f, 0.0f}, {0.0f, 0.0f, 0.0f, 0.0f}};

    stage(0, 0); CPCOMMIT();
    stage(1, 1); CPCOMMIT();

    for (int kt = 0; kt < 16; ++kt) {
        if (kt < 15) CPWAIT1(); else CPWAIT0();
        __syncthreads();
        if (kt < 14) { stage(kt + 2, (kt + 2) % 3); CPCOMMIT(); }

        const int cur = kt % 3;
        const uint32_t ksb = ks0 + cur * KVBUF;
        const uint32_t vsb = vs0 + cur * KVBUF;

#pragma unroll
        for (int qtr = 0; qtr < 4; ++qtr) {     // 32 kv cols per quarter
            // ---- S = Q @ K[qtr]^T : s[mi][4 n8-tiles][4] ----
            float s[2][4][4];
#pragma unroll
            for (int mi = 0; mi < 2; ++mi)
#pragma unroll
                for (int ni = 0; ni < 4; ++ni)
#pragma unroll
                    for (int c = 0; c < 4; ++c) s[mi][ni][c] = 0.0f;

#pragma unroll
            for (int kc = 0; kc < 4; ++kc) {
#pragma unroll
                for (int nb = 0; nb < 2; ++nb) {
                    uint32_t r0, r1, r2, r3;
                    ldm_x4(r0, r1, r2, r3,
                           ksb + (qtr * 32 + nb * 16 + (lj >> 1) * 8 + lr) * KVPIT
                               + (kc * 16 + (lj & 1) * 8) * 2);
#pragma unroll
                    for (int mi = 0; mi < 2; ++mi) {
                        mma_f16(s[mi][2 * nb][0], s[mi][2 * nb][1],
                                s[mi][2 * nb][2], s[mi][2 * nb][3],
                                qf[mi][kc][0], qf[mi][kc][1],
                                qf[mi][kc][2], qf[mi][kc][3], r0, r1);
                        mma_f16(s[mi][2 * nb + 1][0], s[mi][2 * nb + 1][1],
                                s[mi][2 * nb + 1][2], s[mi][2 * nb + 1][3],
                                qf[mi][kc][0], qf[mi][kc][1],
                                qf[mi][kc][2], qf[mi][kc][3], r2, r3);
                    }
                }
            }

            // ---- P = 2^S packed into A-fragments; row sums via ones-MMA ----
            uint32_t pa[2][2][4];
#pragma unroll
            for (int mi = 0; mi < 2; ++mi) {
#pragma unroll
                for (int kc2 = 0; kc2 < 2; ++kc2) {
                    pa[mi][kc2][0] = ex2_h2(cvt_h2(s[mi][2 * kc2][0],     s[mi][2 * kc2][1]));
                    pa[mi][kc2][1] = ex2_h2(cvt_h2(s[mi][2 * kc2][2],     s[mi][2 * kc2][3]));
                    pa[mi][kc2][2] = ex2_h2(cvt_h2(s[mi][2 * kc2 + 1][0], s[mi][2 * kc2 + 1][1]));
                    pa[mi][kc2][3] = ex2_h2(cvt_h2(s[mi][2 * kc2 + 1][2], s[mi][2 * kc2 + 1][3]));
                    mma_f16(osum[mi][0], osum[mi][1], osum[mi][2], osum[mi][3],
                            pa[mi][kc2][0], pa[mi][kc2][1],
                            pa[mi][kc2][2], pa[mi][kc2][3],
                            ONES_H2, ONES_H2);
                }
            }

            // ---- O += P[qtr] @ V[qtr] ----
#pragma unroll
            for (int kc2 = 0; kc2 < 2; ++kc2) {
#pragma unroll
                for (int np = 0; np < 4; ++np) {
                    uint32_t v0, v1, v2, v3;
                    ldm_x4_t(v0, v1, v2, v3,
                             vsb + (qtr * 32 + kc2 * 16 + (lj & 1) * 8 + lr) * KVPIT
                                 + (np * 16 + (lj >> 1) * 8) * 2);
#pragma unroll
                    for (int mi = 0; mi < 2; ++mi) {
                        mma_f16(o[mi][2 * np][0], o[mi][2 * np][1],
                                o[mi][2 * np][2], o[mi][2 * np][3],
                                pa[mi][kc2][0], pa[mi][kc2][1],
                                pa[mi][kc2][2], pa[mi][kc2][3], v0, v1);
                        mma_f16(o[mi][2 * np + 1][0], o[mi][2 * np + 1][1],
                                o[mi][2 * np + 1][2], o[mi][2 * np + 1][3],
                                pa[mi][kc2][0], pa[mi][kc2][1],
                                pa[mi][kc2][2], pa[mi][kc2][3], v2, v3);
                    }
                }
            }
        }
    }

    // Normalize and store fp16
    const int b_ = bh >> 3, h_ = bh & 7;
#pragma unroll
    for (int mi = 0; mi < 2; ++mi) {
        const float inv0 = 1.0f / osum[mi][0];
        const float inv1 = 1.0f / osum[mi][2];
        const int row0 = b_ * 2048 + qt * 128 + warp * 32 + mi * 16 + g;
#pragma unroll
        for (int ni = 0; ni < 8; ++ni) {
            const int col = h_ * 64 + ni * 8 + 2 * t4;
            *(__half2*)&g_atth[(size_t)row0 * 512 + col] =
                __floats2half2_rn(o[mi][ni][0] * inv0, o[mi][ni][1] * inv0);
            *(__half2*)&g_atth[(size_t)(row0 + 8) * 512 + col] =
                __floats2half2_rn(o[mi][ni][2] * inv1, o[mi][ni][3] * inv1);
        }
    }
}

// ---------------------------------------------------------------------------
// Launch
// ---------------------------------------------------------------------------
extern "C" void kernel_launch(void* const* d_in, const int* in_sizes, int n_in,
                              void* d_out, int out_size)
{
    const float* x  = (const float*)d_in[0];
    const float* Wq = (const float*)d_in[1];
    const float* bq = (const float*)d_in[2];
    const float* Wk = (const float*)d_in[3];
    const float* bk = (const float*)d_in[4];
    const float* Wv = (const float*)d_in[5];
    const float* bv = (const float*)d_in[6];
    const float* Wo = (const float*)d_in[7];
    const float* bo = (const float*)d_in[8];
    float* out = (float*)d_out;

    cudaFuncSetAttribute(gemm_f16,
                         cudaFuncAttributeMaxDynamicSharedMemorySize, GEMM_SMEM);
    cudaFuncSetAttribute(attn_f16,
                         cudaFuncAttributeMaxDynamicSharedMemorySize, ATT_SMEM);

    prep_kernel<<<1024, 256>>>(x, Wq, Wk, Wv, Wo);

    gemm_f16<<<dim3(4, 64, 3), 256, GEMM_SMEM>>>(bq, bk, bv, nullptr, 0);

    attn_f16<<<dim3(16, 32), 128, ATT_SMEM>>>();

    gemm_f16<<<dim3(4, 64, 1), 256, GEMM_SMEM>>>(bo, nullptr, nullptr, out, 1);
}